// round 5
// baseline (speedup 1.0000x reference)
#include <cuda_runtime.h>
#include <cstdint>

// LSTM B=4096 T=256 I=8 H=32 O=1.
// NB=2: warp = 2 batches; lane j = hidden unit j. f32x2 lanes are GATE pairs
// {z_i,z_f},{z_g,z_o}. ALL weights in registers (W_hh 128 regs + W_ih 32).
// h and x pre-duplicated ({v,v} u64) in shared -> 1 broadcast LDS per k / per i.
// Sigmoid 0.5 scale folded into weights/biases for gates i,f,o.
// CTA = 64 threads (2 warps, 4 batches), grid = 1024, 6 CTAs/SM target.

#define B_TOT 4096
#define T_TOT 256
#define I_SZ 8
#define CHUNK 16

typedef unsigned long long u64;

__device__ __forceinline__ u64 pack2(float a, float b) {
    u64 r; asm("mov.b64 %0,{%1,%2};" : "=l"(r) : "f"(a), "f"(b)); return r;
}
__device__ __forceinline__ void unpack2(u64 v, float& a, float& b) {
    asm("mov.b64 {%0,%1},%2;" : "=f"(a), "=f"(b) : "l"(v));
}
__device__ __forceinline__ u64 fma2(u64 a, u64 b, u64 c) {
    u64 d; asm("fma.rn.f32x2 %0,%1,%2,%3;" : "=l"(d) : "l"(a), "l"(b), "l"(c)); return d;
}
__device__ __forceinline__ float tanhap(float x) {
    float y; asm("tanh.approx.f32 %0,%1;" : "=f"(y) : "f"(x)); return y;
}
// i,f,o accumulators pre-scaled by 0.5: sigmoid(z)=0.5*tanh(z/2)+0.5
__device__ __forceinline__ float sig_h(float zhalf) {
    return fmaf(0.5f, tanhap(zhalf), 0.5f);
}

__global__ void __launch_bounds__(64, 6)
lstm_kernel(const float* __restrict__ x,
            const float* __restrict__ W_ih,
            const float* __restrict__ W_hh,
            const float* __restrict__ b_ih,
            const float* __restrict__ b_hh,
            const float* __restrict__ W_out,
            const float* __restrict__ b_out,
            float* __restrict__ out)
{
    // per-warp buffers; u64 elements are {v,v} duplicated pairs
    __shared__ __align__(16) u64 xbuf[2][CHUNK * I_SZ * 2];  // [warp][(t*8+i)*2 + b]
    __shared__ __align__(16) u64 hbuf[2][2 * 32 * 2];        // [warp][(cur*32+k)*2 + b]

    const int tid  = threadIdx.x;
    const int lane = tid & 31;
    const int warp = tid >> 5;

    // ---- W_hh rows -> registers as gate pairs (i,f,o pre-scaled by 0.5) ----
    u64 wif[32], wgo[32];
    {
        const float* ri = W_hh + (0 * 32 + lane) * 32;
        const float* rf = W_hh + (1 * 32 + lane) * 32;
        const float* rg = W_hh + (2 * 32 + lane) * 32;
        const float* ro = W_hh + (3 * 32 + lane) * 32;
#pragma unroll
        for (int kk = 0; kk < 8; ++kk) {
            const float4 ai = *(const float4*)(ri + kk * 4);
            const float4 af = *(const float4*)(rf + kk * 4);
            const float4 ag = *(const float4*)(rg + kk * 4);
            const float4 ao = *(const float4*)(ro + kk * 4);
            wif[kk * 4 + 0] = pack2(0.5f * ai.x, 0.5f * af.x);
            wif[kk * 4 + 1] = pack2(0.5f * ai.y, 0.5f * af.y);
            wif[kk * 4 + 2] = pack2(0.5f * ai.z, 0.5f * af.z);
            wif[kk * 4 + 3] = pack2(0.5f * ai.w, 0.5f * af.w);
            wgo[kk * 4 + 0] = pack2(ag.x, 0.5f * ao.x);
            wgo[kk * 4 + 1] = pack2(ag.y, 0.5f * ao.y);
            wgo[kk * 4 + 2] = pack2(ag.z, 0.5f * ao.z);
            wgo[kk * 4 + 3] = pack2(ag.w, 0.5f * ao.w);
        }
    }

    // ---- W_ih -> registers as gate pairs ----
    u64 wiif[I_SZ], wigo[I_SZ];
#pragma unroll
    for (int i = 0; i < I_SZ; ++i) {
        const float a = 0.5f * W_ih[(0 * 32 + lane) * I_SZ + i];
        const float b = 0.5f * W_ih[(1 * 32 + lane) * I_SZ + i];
        const float c =        W_ih[(2 * 32 + lane) * I_SZ + i];
        const float d = 0.5f * W_ih[(3 * 32 + lane) * I_SZ + i];
        wiif[i] = pack2(a, b);
        wigo[i] = pack2(c, d);
    }

    // ---- zero h buffers ----
    {
        u64* hb = hbuf[warp];
        hb[lane * 4 + 0] = 0ull; hb[lane * 4 + 1] = 0ull;
        hb[lane * 4 + 2] = 0ull; hb[lane * 4 + 3] = 0ull;
    }

    // ---- biases (gate pairs, i/f/o pre-scaled) ----
    const float bi_ = 0.5f * (b_ih[0 * 32 + lane] + b_hh[0 * 32 + lane]);
    const float bf_ = 0.5f * (b_ih[1 * 32 + lane] + b_hh[1 * 32 + lane]);
    const float bg_ =         b_ih[2 * 32 + lane] + b_hh[2 * 32 + lane];
    const float bo_ = 0.5f * (b_ih[3 * 32 + lane] + b_hh[3 * 32 + lane]);
    const u64 bif = pack2(bi_, bf_);
    const u64 bgo = pack2(bg_, bo_);

    float c0 = 0.f, c1 = 0.f;
    float h0 = 0.f, h1 = 0.f;

    u64* const xA = xbuf[warp];
    u64* const hA = hbuf[warp];
    int cur = 0;

    const float* xw = x + (size_t)(blockIdx.x * 4 + warp * 2) * T_TOT * I_SZ;
    const int t_ = lane >> 1;           // 0..15
    const int i0 = (lane & 1) * 4;      // 0 or 4

#pragma unroll 1
    for (int tc = 0; tc < T_TOT / CHUNK; ++tc) {
        __syncwarp();
        // ---- stage x chunk, pre-duplicated {x,x}; lane covers (t_, i0..i0+3) ----
#pragma unroll
        for (int b = 0; b < 2; ++b) {
            const float4 v = *(const float4*)(xw
                + ((size_t)b * T_TOT + tc * CHUNK + t_) * I_SZ + i0);
            xA[((t_ * I_SZ + i0 + 0) * 2) + b] = pack2(v.x, v.x);
            xA[((t_ * I_SZ + i0 + 1) * 2) + b] = pack2(v.y, v.y);
            xA[((t_ * I_SZ + i0 + 2) * 2) + b] = pack2(v.z, v.z);
            xA[((t_ * I_SZ + i0 + 3) * 2) + b] = pack2(v.w, v.w);
        }
        __syncwarp();

#pragma unroll 1
        for (int s = 0; s < CHUNK; ++s) {
            u64 zif0 = bif, zif1 = bif;
            u64 zgo0 = bgo, zgo1 = bgo;

            // ---- input projection: broadcast dup-x, register weights ----
#pragma unroll
            for (int i = 0; i < I_SZ; ++i) {
                const ulonglong2 xv = *(const ulonglong2*)(xA + (s * I_SZ + i) * 2);
                zif0 = fma2(xv.x, wiif[i], zif0); zgo0 = fma2(xv.x, wigo[i], zgo0);
                zif1 = fma2(xv.y, wiif[i], zif1); zgo1 = fma2(xv.y, wigo[i], zgo1);
            }

            // ---- recurrent projection: broadcast dup-h, register weights ----
#pragma unroll
            for (int k = 0; k < 32; ++k) {
                const ulonglong2 hv = *(const ulonglong2*)(hA + (cur * 32 + k) * 2);
                zif0 = fma2(hv.x, wif[k], zif0); zgo0 = fma2(hv.x, wgo[k], zgo0);
                zif1 = fma2(hv.y, wif[k], zif1); zgo1 = fma2(hv.y, wgo[k], zgo1);
            }

            // ---- gates + state update ----
            const int nxt = cur ^ 1;
            float zi, zf, zg, zo;

            unpack2(zif0, zi, zf); unpack2(zgo0, zg, zo);
            c0 = fmaf(sig_h(zf), c0, sig_h(zi) * tanhap(zg));
            h0 = sig_h(zo) * tanhap(c0);

            unpack2(zif1, zi, zf); unpack2(zgo1, zg, zo);
            c1 = fmaf(sig_h(zf), c1, sig_h(zi) * tanhap(zg));
            h1 = sig_h(zo) * tanhap(c1);

            // store duplicated h for next step (16B/lane, conflict-free)
            *(float4*)(hA + (nxt * 32 + lane) * 2) = make_float4(h0, h0, h1, h1);
            cur = nxt;
            __syncwarp();
        }
    }

    // ---- output head: out[b] = sum_j h[b][j]*W_out[j] + b_out ----
    const float wo = W_out[lane];
    float v0 = h0 * wo, v1 = h1 * wo;
#pragma unroll
    for (int off = 16; off; off >>= 1) {
        v0 += __shfl_xor_sync(0xffffffffu, v0, off);
        v1 += __shfl_xor_sync(0xffffffffu, v1, off);
    }
    if (lane == 0) {
        const float bout = b_out[0];
        const int bb = blockIdx.x * 4 + warp * 2;
        out[bb + 0] = v0 + bout;
        out[bb + 1] = v1 + bout;
    }
}

extern "C" void kernel_launch(void* const* d_in, const int* in_sizes, int n_in,
                              void* d_out, int out_size)
{
    const float* x     = (const float*)d_in[0];
    const float* W_ih  = (const float*)d_in[1];
    const float* W_hh  = (const float*)d_in[2];
    const float* b_ih  = (const float*)d_in[3];
    const float* b_hh  = (const float*)d_in[4];
    const float* W_out = (const float*)d_in[5];
    const float* b_out = (const float*)d_in[6];
    float* out = (float*)d_out;

    lstm_kernel<<<B_TOT / 4, 64>>>(x, W_ih, W_hh, b_ih, b_hh, W_out, b_out, out);
}

// round 6
// speedup vs baseline: 1.7193x; 1.7193x over previous
#include <cuda_runtime.h>
#include <cstdint>

// LSTM B=4096 T=256 I=8 H=32 O=1.
// Warp = 4 batches; lane j = hidden unit j. f32x2 lanes are GATE pairs
// {z_i,z_f},{z_g,z_o}. W_hh in 128 regs as gate pairs; W_ih in smem.
// h and x pre-duplicated ({v,v} u64) in shared -> broadcast loads, zero packs.
// Cross-step software pipeline: xacc = bias + W_ih x_{s+1} is computed in the
// shadow of step s's activation tail, so the MUFU/dependency chain overlaps
// with independent FMA work. Sigmoid 0.5 folded into weights/biases (i,f,o).
// CTA = 128 threads (4 independent warps). Grid = 256.

#define B_TOT 4096
#define T_TOT 256
#define I_SZ 8
#define CHUNK 16

typedef unsigned long long u64;

__device__ __forceinline__ u64 pack2(float a, float b) {
    u64 r; asm("mov.b64 %0,{%1,%2};" : "=l"(r) : "f"(a), "f"(b)); return r;
}
__device__ __forceinline__ void unpack2(u64 v, float& a, float& b) {
    asm("mov.b64 {%0,%1},%2;" : "=f"(a), "=f"(b) : "l"(v));
}
__device__ __forceinline__ u64 fma2(u64 a, u64 b, u64 c) {
    u64 d; asm("fma.rn.f32x2 %0,%1,%2,%3;" : "=l"(d) : "l"(a), "l"(b), "l"(c)); return d;
}
__device__ __forceinline__ float tanhap(float x) {
    float y; asm("tanh.approx.f32 %0,%1;" : "=f"(y) : "f"(x)); return y;
}
// i,f,o accumulators pre-scaled by 0.5: sigmoid(z)=0.5*tanh(z/2)+0.5
__device__ __forceinline__ float sig_h(float zhalf) {
    return fmaf(0.5f, tanhap(zhalf), 0.5f);
}

__global__ void __launch_bounds__(128, 2)
lstm_kernel(const float* __restrict__ x,
            const float* __restrict__ W_ih,
            const float* __restrict__ W_hh,
            const float* __restrict__ b_ih,
            const float* __restrict__ b_hh,
            const float* __restrict__ W_out,
            const float* __restrict__ b_out,
            float* __restrict__ out)
{
    __shared__ __align__(16) ulonglong2 wi_sm[I_SZ * 32];       // [i][j] {wif},{wgo}
    __shared__ __align__(16) u64 xbuf[4][2][CHUNK * I_SZ * 2];  // [warp][b01/b23][t][i][pair]
    __shared__ __align__(16) u64 hbuf[4][2][2 * 32 * 2];        // [warp][b01/b23][cur][k][pair]

    const int tid  = threadIdx.x;
    const int lane = tid & 31;
    const int warp = tid >> 5;

    // ---- W_hh rows -> registers as gate pairs (i,f,o pre-scaled by 0.5) ----
    u64 wif[32], wgo[32];
    {
        const float* ri = W_hh + (0 * 32 + lane) * 32;
        const float* rf = W_hh + (1 * 32 + lane) * 32;
        const float* rg = W_hh + (2 * 32 + lane) * 32;
        const float* ro = W_hh + (3 * 32 + lane) * 32;
#pragma unroll
        for (int kk = 0; kk < 8; ++kk) {
            const float4 ai = *(const float4*)(ri + kk * 4);
            const float4 af = *(const float4*)(rf + kk * 4);
            const float4 ag = *(const float4*)(rg + kk * 4);
            const float4 ao = *(const float4*)(ro + kk * 4);
            wif[kk * 4 + 0] = pack2(0.5f * ai.x, 0.5f * af.x);
            wif[kk * 4 + 1] = pack2(0.5f * ai.y, 0.5f * af.y);
            wif[kk * 4 + 2] = pack2(0.5f * ai.z, 0.5f * af.z);
            wif[kk * 4 + 3] = pack2(0.5f * ai.w, 0.5f * af.w);
            wgo[kk * 4 + 0] = pack2(ag.x, 0.5f * ao.x);
            wgo[kk * 4 + 1] = pack2(ag.y, 0.5f * ao.y);
            wgo[kk * 4 + 2] = pack2(ag.z, 0.5f * ao.z);
            wgo[kk * 4 + 3] = pack2(ag.w, 0.5f * ao.w);
        }
    }

    // ---- W_ih gate pairs into smem ----
    for (int idx = tid; idx < I_SZ * 32; idx += 128) {
        int i = idx >> 5, j = idx & 31;
        float a = 0.5f * W_ih[(0 * 32 + j) * I_SZ + i];
        float b = 0.5f * W_ih[(1 * 32 + j) * I_SZ + i];
        float c =        W_ih[(2 * 32 + j) * I_SZ + i];
        float d = 0.5f * W_ih[(3 * 32 + j) * I_SZ + i];
        wi_sm[idx] = make_ulonglong2(pack2(a, b), pack2(c, d));
    }
    // ---- zero h buffers ----
    for (int idx = tid; idx < 4 * 2 * 2 * 32 * 2; idx += 128)
        ((u64*)hbuf)[idx] = 0ull;
    __syncthreads();

    // ---- biases (gate pairs, i/f/o pre-scaled) ----
    const float bi_ = 0.5f * (b_ih[0 * 32 + lane] + b_hh[0 * 32 + lane]);
    const float bf_ = 0.5f * (b_ih[1 * 32 + lane] + b_hh[1 * 32 + lane]);
    const float bg_ =         b_ih[2 * 32 + lane] + b_hh[2 * 32 + lane];
    const float bo_ = 0.5f * (b_ih[3 * 32 + lane] + b_hh[3 * 32 + lane]);
    const u64 bif = pack2(bi_, bf_);
    const u64 bgo = pack2(bg_, bo_);

    float c0 = 0.f, c1 = 0.f, c2 = 0.f, c3 = 0.f;
    float h0 = 0.f, h1 = 0.f, h2 = 0.f, h3 = 0.f;

    u64* const xA = xbuf[warp][0];
    u64* const xB = xbuf[warp][1];
    u64* const hA = hbuf[warp][0];
    u64* const hB = hbuf[warp][1];
    int cur = 0;

    const float* xw = x + (size_t)(blockIdx.x * 16 + warp * 4) * T_TOT * I_SZ;
    const int t_ = lane >> 1;
    const int i0 = (lane & 1) * 4;

    // next-step input-projection accumulators (software pipeline)
    u64 nif0, nif1, nif2, nif3, ngo0, ngo1, ngo2, ngo3;

    // macro-ish lambdas
    auto xproj = [&](int s) {
        nif0 = bif; nif1 = bif; nif2 = bif; nif3 = bif;
        ngo0 = bgo; ngo1 = bgo; ngo2 = bgo; ngo3 = bgo;
#pragma unroll
        for (int i = 0; i < I_SZ; ++i) {
            const ulonglong2 x01 = *(const ulonglong2*)(xA + (s * I_SZ + i) * 2);
            const ulonglong2 x23 = *(const ulonglong2*)(xB + (s * I_SZ + i) * 2);
            const ulonglong2 wv  = wi_sm[i * 32 + lane];
            nif0 = fma2(x01.x, wv.x, nif0); ngo0 = fma2(x01.x, wv.y, ngo0);
            nif1 = fma2(x01.y, wv.x, nif1); ngo1 = fma2(x01.y, wv.y, ngo1);
            nif2 = fma2(x23.x, wv.x, nif2); ngo2 = fma2(x23.x, wv.y, ngo2);
            nif3 = fma2(x23.y, wv.x, nif3); ngo3 = fma2(x23.y, wv.y, ngo3);
        }
    };

#pragma unroll 1
    for (int tc = 0; tc < T_TOT / CHUNK; ++tc) {
        __syncwarp();
        // ---- stage x chunk, pre-duplicated {x,x} ----
#pragma unroll
        for (int b = 0; b < 4; ++b) {
            const float4 v = *(const float4*)(xw
                + ((size_t)b * T_TOT + tc * CHUNK + t_) * I_SZ + i0);
            u64* dst = (b < 2) ? xA : xB;
            const int p = b & 1;
            dst[(t_ * I_SZ + i0 + 0) * 2 + p] = pack2(v.x, v.x);
            dst[(t_ * I_SZ + i0 + 1) * 2 + p] = pack2(v.y, v.y);
            dst[(t_ * I_SZ + i0 + 2) * 2 + p] = pack2(v.z, v.z);
            dst[(t_ * I_SZ + i0 + 3) * 2 + p] = pack2(v.w, v.w);
        }
        __syncwarp();

        xproj(0);   // prime pipeline for s=0

#pragma unroll 1
        for (int s = 0; s < CHUNK; ++s) {
            // z starts from pipelined x projection
            u64 zif0 = nif0, zif1 = nif1, zif2 = nif2, zif3 = nif3;
            u64 zgo0 = ngo0, zgo1 = ngo1, zgo2 = ngo2, zgo3 = ngo3;

            // ---- recurrent projection: register weights, broadcast dup-h ----
#pragma unroll
            for (int k = 0; k < 32; ++k) {
                const ulonglong2 h01 = *(const ulonglong2*)(hA + (cur * 32 + k) * 2);
                const ulonglong2 h23 = *(const ulonglong2*)(hB + (cur * 32 + k) * 2);
                zif0 = fma2(h01.x, wif[k], zif0); zgo0 = fma2(h01.x, wgo[k], zgo0);
                zif1 = fma2(h01.y, wif[k], zif1); zgo1 = fma2(h01.y, wgo[k], zgo1);
                zif2 = fma2(h23.x, wif[k], zif2); zgo2 = fma2(h23.x, wgo[k], zgo2);
                zif3 = fma2(h23.y, wif[k], zif3); zgo3 = fma2(h23.y, wgo[k], zgo3);
            }

            // ---- next step's x projection: independent work that overlaps
            //      with the activation dependency chain below ----
            if (s < CHUNK - 1) xproj(s + 1);

            // ---- gates + state update ----
            const int nxt = cur ^ 1;
            float zi, zf, zg, zo;

            unpack2(zif0, zi, zf); unpack2(zgo0, zg, zo);
            c0 = fmaf(sig_h(zf), c0, sig_h(zi) * tanhap(zg));
            h0 = sig_h(zo) * tanhap(c0);

            unpack2(zif1, zi, zf); unpack2(zgo1, zg, zo);
            c1 = fmaf(sig_h(zf), c1, sig_h(zi) * tanhap(zg));
            h1 = sig_h(zo) * tanhap(c1);

            unpack2(zif2, zi, zf); unpack2(zgo2, zg, zo);
            c2 = fmaf(sig_h(zf), c2, sig_h(zi) * tanhap(zg));
            h2 = sig_h(zo) * tanhap(c2);

            unpack2(zif3, zi, zf); unpack2(zgo3, zg, zo);
            c3 = fmaf(sig_h(zf), c3, sig_h(zi) * tanhap(zg));
            h3 = sig_h(zo) * tanhap(c3);

            // store duplicated h for next step (conflict-free, 16B/lane)
            *(float4*)(hA + (nxt * 32 + lane) * 2) = make_float4(h0, h0, h1, h1);
            *(float4*)(hB + (nxt * 32 + lane) * 2) = make_float4(h2, h2, h3, h3);
            cur = nxt;
            __syncwarp();
        }
    }

    // ---- output head: out[b] = sum_j h[b][j]*W_out[j] + b_out ----
    const float wo = W_out[lane];
    float v0 = h0 * wo, v1 = h1 * wo, v2 = h2 * wo, v3 = h3 * wo;
#pragma unroll
    for (int off = 16; off; off >>= 1) {
        v0 += __shfl_xor_sync(0xffffffffu, v0, off);
        v1 += __shfl_xor_sync(0xffffffffu, v1, off);
        v2 += __shfl_xor_sync(0xffffffffu, v2, off);
        v3 += __shfl_xor_sync(0xffffffffu, v3, off);
    }
    if (lane == 0) {
        const float bout = b_out[0];
        const int bb = blockIdx.x * 16 + warp * 4;
        out[bb + 0] = v0 + bout;
        out[bb + 1] = v1 + bout;
        out[bb + 2] = v2 + bout;
        out[bb + 3] = v3 + bout;
    }
}

extern "C" void kernel_launch(void* const* d_in, const int* in_sizes, int n_in,
                              void* d_out, int out_size)
{
    const float* x     = (const float*)d_in[0];
    const float* W_ih  = (const float*)d_in[1];
    const float* W_hh  = (const float*)d_in[2];
    const float* b_ih  = (const float*)d_in[3];
    const float* b_hh  = (const float*)d_in[4];
    const float* W_out = (const float*)d_in[5];
    const float* b_out = (const float*)d_in[6];
    float* out = (float*)d_out;

    lstm_kernel<<<B_TOT / 16, 128>>>(x, W_ih, W_hh, b_ih, b_hh, W_out, b_out, out);
}

// round 7
// speedup vs baseline: 1.8310x; 1.0649x over previous
#include <cuda_runtime.h>
#include <cstdint>

// LSTM B=4096 T=256 I=8 H=32 O=1.
// NB=8: warp = 8 batches; lane j = hidden unit j. f32x2 lanes are GATE pairs
// {z_i,z_f},{z_g,z_o}; 16 independent fma2 accumulator chains per warp give a
// single warp enough ILP to self-saturate the fma pipe (1 warp/SMSP).
// W_hh in 128 regs as gate pairs; W_ih in smem. h and x pre-duplicated
// ({v,v} u64) in shared -> broadcast LDS.128, zero packs in hot loop.
// Sigmoid 0.5 folded into weights/biases (i,f,o).
// CTA = 128 thr (4 warps, 32 batches), grid = 128 -> exactly 1 CTA per SM.

#define B_TOT 4096
#define T_TOT 256
#define I_SZ 8
#define CHUNK 8

// shared strides (in u64 units)
#define HK_STRIDE 10            // 8 batch-dups + 2 pad; 80B, 16B-aligned
#define XI_STRIDE 10
#define XT_STRIDE 82            // 8*10 + 2 pad; 656B, 16B-aligned

typedef unsigned long long u64;

__device__ __forceinline__ u64 pack2(float a, float b) {
    u64 r; asm("mov.b64 %0,{%1,%2};" : "=l"(r) : "f"(a), "f"(b)); return r;
}
__device__ __forceinline__ void unpack2(u64 v, float& a, float& b) {
    asm("mov.b64 {%0,%1},%2;" : "=f"(a), "=f"(b) : "l"(v));
}
__device__ __forceinline__ u64 fma2(u64 a, u64 b, u64 c) {
    u64 d; asm("fma.rn.f32x2 %0,%1,%2,%3;" : "=l"(d) : "l"(a), "l"(b), "l"(c)); return d;
}
__device__ __forceinline__ float tanhap(float x) {
    float y; asm("tanh.approx.f32 %0,%1;" : "=f"(y) : "f"(x)); return y;
}
// i,f,o accumulators pre-scaled by 0.5: sigmoid(z)=0.5*tanh(z/2)+0.5
__device__ __forceinline__ float sig_h(float zhalf) {
    return fmaf(0.5f, tanhap(zhalf), 0.5f);
}

__global__ void __launch_bounds__(128)
lstm_kernel(const float* __restrict__ x,
            const float* __restrict__ W_ih,
            const float* __restrict__ W_hh,
            const float* __restrict__ b_ih,
            const float* __restrict__ b_hh,
            const float* __restrict__ W_out,
            const float* __restrict__ b_out,
            float* __restrict__ out)
{
    __shared__ __align__(16) ulonglong2 wi_sm[I_SZ * 32];        // [i][j] {wif},{wgo}
    __shared__ __align__(16) u64 xbuf[4][CHUNK * XT_STRIDE];     // per-warp x dup
    __shared__ __align__(16) u64 hbuf[4][2 * 32 * HK_STRIDE];    // per-warp h dup, dbl-buf

    const int tid  = threadIdx.x;
    const int lane = tid & 31;
    const int warp = tid >> 5;

    // ---- W_hh rows -> registers as gate pairs (i,f,o pre-scaled by 0.5) ----
    u64 wif[32], wgo[32];
    {
        const float* ri = W_hh + (0 * 32 + lane) * 32;
        const float* rf = W_hh + (1 * 32 + lane) * 32;
        const float* rg = W_hh + (2 * 32 + lane) * 32;
        const float* ro = W_hh + (3 * 32 + lane) * 32;
#pragma unroll
        for (int kk = 0; kk < 8; ++kk) {
            const float4 ai = *(const float4*)(ri + kk * 4);
            const float4 af = *(const float4*)(rf + kk * 4);
            const float4 ag = *(const float4*)(rg + kk * 4);
            const float4 ao = *(const float4*)(ro + kk * 4);
            wif[kk * 4 + 0] = pack2(0.5f * ai.x, 0.5f * af.x);
            wif[kk * 4 + 1] = pack2(0.5f * ai.y, 0.5f * af.y);
            wif[kk * 4 + 2] = pack2(0.5f * ai.z, 0.5f * af.z);
            wif[kk * 4 + 3] = pack2(0.5f * ai.w, 0.5f * af.w);
            wgo[kk * 4 + 0] = pack2(ag.x, 0.5f * ao.x);
            wgo[kk * 4 + 1] = pack2(ag.y, 0.5f * ao.y);
            wgo[kk * 4 + 2] = pack2(ag.z, 0.5f * ao.z);
            wgo[kk * 4 + 3] = pack2(ag.w, 0.5f * ao.w);
        }
    }

    // ---- W_ih gate pairs into smem ----
    for (int idx = tid; idx < I_SZ * 32; idx += 128) {
        int i = idx >> 5, j = idx & 31;
        float a = 0.5f * W_ih[(0 * 32 + j) * I_SZ + i];
        float b = 0.5f * W_ih[(1 * 32 + j) * I_SZ + i];
        float c =        W_ih[(2 * 32 + j) * I_SZ + i];
        float d = 0.5f * W_ih[(3 * 32 + j) * I_SZ + i];
        wi_sm[idx] = make_ulonglong2(pack2(a, b), pack2(c, d));
    }
    // ---- zero h buffers ----
    for (int idx = tid; idx < 4 * 2 * 32 * HK_STRIDE; idx += 128)
        ((u64*)hbuf)[idx] = 0ull;
    __syncthreads();

    // ---- biases (gate pairs, i/f/o pre-scaled) ----
    const float bi_ = 0.5f * (b_ih[0 * 32 + lane] + b_hh[0 * 32 + lane]);
    const float bf_ = 0.5f * (b_ih[1 * 32 + lane] + b_hh[1 * 32 + lane]);
    const float bg_ =         b_ih[2 * 32 + lane] + b_hh[2 * 32 + lane];
    const float bo_ = 0.5f * (b_ih[3 * 32 + lane] + b_hh[3 * 32 + lane]);
    const u64 bif = pack2(bi_, bf_);
    const u64 bgo = pack2(bg_, bo_);

    float cs[8], hs[8];
#pragma unroll
    for (int b = 0; b < 8; ++b) { cs[b] = 0.f; hs[b] = 0.f; }

    u64* const xW = xbuf[warp];
    u64* const hW = hbuf[warp];
    int cur = 0;

    // this warp's 8 batches
    const float* xw = x + (size_t)(blockIdx.x * 32 + warp * 8) * T_TOT * I_SZ;
    const int t_ = lane >> 2;           // 0..7
    const int i0 = (lane & 3) * 2;      // 0,2,4,6

#pragma unroll 1
    for (int tc = 0; tc < T_TOT / CHUNK; ++tc) {
        __syncwarp();
        // ---- stage x chunk, pre-duplicated {x,x}; lane covers (t_, i0..i0+1) ----
#pragma unroll
        for (int b = 0; b < 8; ++b) {
            const float2 v = *(const float2*)(xw
                + ((size_t)b * T_TOT + tc * CHUNK + t_) * I_SZ + i0);
            xW[t_ * XT_STRIDE + (i0 + 0) * XI_STRIDE + b] = pack2(v.x, v.x);
            xW[t_ * XT_STRIDE + (i0 + 1) * XI_STRIDE + b] = pack2(v.y, v.y);
        }
        __syncwarp();

#pragma unroll 1
        for (int s = 0; s < CHUNK; ++s) {
            const u64* hr = hW + cur * (32 * HK_STRIDE);
            u64*       hw = hW + (cur ^ 1) * (32 * HK_STRIDE);

            u64 zif[8], zgo[8];
#pragma unroll
            for (int b = 0; b < 8; ++b) { zif[b] = bif; zgo[b] = bgo; }

            // ---- input projection: broadcast dup-x, per-lane smem weights ----
#pragma unroll
            for (int i = 0; i < I_SZ; ++i) {
                const ulonglong2 wv = wi_sm[i * 32 + lane];
                const u64* xr = xW + s * XT_STRIDE + i * XI_STRIDE;
#pragma unroll
                for (int p = 0; p < 4; ++p) {
                    const ulonglong2 xv = *(const ulonglong2*)(xr + 2 * p);
                    zif[2*p+0] = fma2(xv.x, wv.x, zif[2*p+0]);
                    zgo[2*p+0] = fma2(xv.x, wv.y, zgo[2*p+0]);
                    zif[2*p+1] = fma2(xv.y, wv.x, zif[2*p+1]);
                    zgo[2*p+1] = fma2(xv.y, wv.y, zgo[2*p+1]);
                }
            }

            // ---- recurrent projection: register weights, broadcast dup-h ----
#pragma unroll
            for (int k = 0; k < 32; ++k) {
                const u64 wifk = wif[k], wgok = wgo[k];
                const u64* hk = hr + k * HK_STRIDE;
#pragma unroll
                for (int p = 0; p < 4; ++p) {
                    const ulonglong2 hv = *(const ulonglong2*)(hk + 2 * p);
                    zif[2*p+0] = fma2(hv.x, wifk, zif[2*p+0]);
                    zgo[2*p+0] = fma2(hv.x, wgok, zgo[2*p+0]);
                    zif[2*p+1] = fma2(hv.y, wifk, zif[2*p+1]);
                    zgo[2*p+1] = fma2(hv.y, wgok, zgo[2*p+1]);
                }
            }

            // ---- gates + state update (8 independent chains) ----
#pragma unroll
            for (int b = 0; b < 8; ++b) {
                float zi, zf, zg, zo;
                unpack2(zif[b], zi, zf); unpack2(zgo[b], zg, zo);
                cs[b] = fmaf(sig_h(zf), cs[b], sig_h(zi) * tanhap(zg));
                hs[b] = sig_h(zo) * tanhap(cs[b]);
            }

            // ---- store duplicated h for next step: 4x STS.128, stride-10 ----
            {
                u64* hd = hw + lane * HK_STRIDE;
                *(float4*)(hd + 0) = make_float4(hs[0], hs[0], hs[1], hs[1]);
                *(float4*)(hd + 2) = make_float4(hs[2], hs[2], hs[3], hs[3]);
                *(float4*)(hd + 4) = make_float4(hs[4], hs[4], hs[5], hs[5]);
                *(float4*)(hd + 6) = make_float4(hs[6], hs[6], hs[7], hs[7]);
            }
            cur ^= 1;
            __syncwarp();
        }
    }

    // ---- output head: out[b] = sum_j h[b][j]*W_out[j] + b_out ----
    const float wo = W_out[lane];
    float v[8];
#pragma unroll
    for (int b = 0; b < 8; ++b) v[b] = hs[b] * wo;
#pragma unroll
    for (int off = 16; off; off >>= 1) {
#pragma unroll
        for (int b = 0; b < 8; ++b)
            v[b] += __shfl_xor_sync(0xffffffffu, v[b], off);
    }
    if (lane == 0) {
        const float bout = b_out[0];
        const int bb = blockIdx.x * 32 + warp * 8;
#pragma unroll
        for (int b = 0; b < 8; ++b) out[bb + b] = v[b] + bout;
    }
}

extern "C" void kernel_launch(void* const* d_in, const int* in_sizes, int n_in,
                              void* d_out, int out_size)
{
    const float* x     = (const float*)d_in[0];
    const float* W_ih  = (const float*)d_in[1];
    const float* W_hh  = (const float*)d_in[2];
    const float* b_ih  = (const float*)d_in[3];
    const float* b_hh  = (const float*)d_in[4];
    const float* W_out = (const float*)d_in[5];
    const float* b_out = (const float*)d_in[6];
    float* out = (float*)d_out;

    lstm_kernel<<<B_TOT / 32, 128>>>(x, W_ih, W_hh, b_ih, b_hh, W_out, b_out, out);
}